// round 8
// baseline (speedup 1.0000x reference)
#include <cuda_runtime.h>
#include <math.h>

// Problem dims
#define Bz 64
#define Sz 1024
#define Dz 64
#define Hz 512
#define Az 16

// Persistent kernel config
#define NBLK 128
#define NTHR 256
#define PITCH 644                    // smem row pitch in floats (mult of 4, %32==4 -> conflict-free LDS.128)
#define SMEM_BYTES (32 * PITCH * 4)  // 82432 B

// d_out layout: q [B,S,A] | cb_preds [B,S,D] | hidden [B,H] | ca1_out [B,S,H]
#define QOFF   0
#define CBOFF  (Bz * Sz * Az)             // 1048576
#define HIDOFF (CBOFF + Bz * Sz * Dz)     // 5242880
#define CA1OFF (HIDOFF + Bz * Hz)         // 5275648

// ---------------- device scratch (static __device__ only; no allocs) ----------------
__device__ float g_outs[Sz * Bz * Hz];   // h_t for all t, layout [t][b][j]  (134 MB)
__device__ float g_a[Bz * Hz];           // per-step hidden of callback MLP
__device__ float g_wpack[3 * Hz * 640];  // packed gate weights [gate][k][j]; j: 0..511=h, 512..575=x, 576..639=pred
__device__ float g_bsum[2 * Hz];         // b_ih+b_hh for r,z gates
__device__ float g_bin[Hz];              // b_ih for n gate
__device__ float g_bhn[Hz];              // b_hh for n gate
__device__ float g_zero[Bz * Hz];        // NEVER written -> guaranteed zeros (h0 / pred0)
__device__ unsigned long long g_bar;     // grid barrier counter

__global__ void reset_kernel() {
    if (threadIdx.x == 0) g_bar = 0ULL;
}

__device__ __forceinline__ float4 ldcg4(const float4* p) { return __ldcg(p); }

// Grid-wide epoch barrier. All NBLK CTAs are co-resident (1 CTA/SM, NBLK <= SM count).
__device__ __forceinline__ void gsync(unsigned long long& target) {
    __syncthreads();
    if (threadIdx.x == 0) {
        __threadfence();
        target += (unsigned long long)NBLK;
        atomicAdd(&g_bar, 1ULL);
        while (*(volatile unsigned long long*)&g_bar < target) __nanosleep(40);
    }
    __syncthreads();
}

// dot-product accumulate: acc += dot(va, vb) — fused FFMA chain, no macro token capture
__device__ __forceinline__ void fma4(float& acc, const float4 va, const float4 vb) {
    acc = fmaf(va.x, vb.x, acc);
    acc = fmaf(va.y, vb.y, acc);
    acc = fmaf(va.z, vb.z, acc);
    acc = fmaf(va.w, vb.w, acc);
}

__device__ __forceinline__ float sigmoidf_(float v) { return 1.0f / (1.0f + expf(-v)); }

// =====================================================================================
// Persistent recurrent kernel: whole time loop with internal grid barriers.
// Stage1: h_new[64,512]  = GRU gates from [x_t | pred_{t-1} | h_{t-1}] (K=640)
// Stage2: a[64,512]      = relu(h_new @ cb_w1^T + cb_b1)
// Stage3: pred[64,64]    = a @ cb_w2^T + cb_b2  -> written straight into d_out cb region
// =====================================================================================
__global__ void __launch_bounds__(NTHR, 1) recur_kernel(
    const float* __restrict__ x,      // [B,S,D]
    const float* __restrict__ W_ih,   // [3H, 2D]
    const float* __restrict__ W_hh,   // [3H, H]
    const float* __restrict__ b_ih,   // [3H]
    const float* __restrict__ b_hh,   // [3H]
    const float* __restrict__ cb_w1,  // [H,H]
    const float* __restrict__ cb_b1,  // [H]
    const float* __restrict__ cb_w2,  // [D,H]
    const float* __restrict__ cb_b2,  // [D]
    float* __restrict__ out_cb,       // d_out + CBOFF  [B,S,D]
    float* __restrict__ out_hid)      // d_out + HIDOFF [B,H]
{
    extern __shared__ float sh[];  // 32 rows x PITCH floats
    const int tid  = threadIdx.x;
    const int bid  = blockIdx.x;
    const int lane = tid & 31;
    const int warp = tid >> 5;
    unsigned long long target = 0ULL;

    // ---------------- pack gate weights + biases (cheap, every launch) ----------------
    for (int idx = bid * NTHR + tid; idx < 3 * Hz * 640; idx += NBLK * NTHR) {
        int j = idx % 640;
        int k = (idx / 640) % Hz;
        int g = idx / (640 * Hz);
        float v;
        if (j < 512) v = W_hh[(g * Hz + k) * Hz + j];
        else         v = W_ih[(g * Hz + k) * (2 * Dz) + (j - 512)];
        g_wpack[idx] = v;
    }
    for (int k = bid * NTHR + tid; k < Hz; k += NBLK * NTHR) {
        g_bsum[k]      = b_ih[k] + b_hh[k];
        g_bsum[Hz + k] = b_ih[Hz + k] + b_hh[Hz + k];
        g_bin[k]       = b_ih[2 * Hz + k];
        g_bhn[k]       = b_hh[2 * Hz + k];
    }
    gsync(target);

    const int kb = bid >> 1;         // k-chunk (8 wide) index, 0..63
    const int b0 = (bid & 1) * 32;   // batch half

    for (int t = 0; t < Sz; t++) {
        // =========================== Stage 1: gates -> h_new ===========================
        {
            const float* hsrc = t ? (g_outs + (size_t)(t - 1) * Bz * Hz) : g_zero;
            // smem rows: [0:512)=h, [512:576)=x_t, [576:640)=pred_{t-1}; 160 float4/row
            const int row = tid >> 3, q = tid & 7;
            {
                const int bg = b0 + row;
                const float4* hp = (const float4*)(hsrc + bg * Hz);
                const float4* xp = (const float4*)(x + ((size_t)bg * Sz + t) * Dz);
                const float4* pp = t ? (const float4*)(out_cb + (size_t)bg * Sz * Dz + (size_t)(t - 1) * Dz)
                                     : (const float4*)(g_zero + bg * Dz);
                float4* dst = (float4*)(sh + row * PITCH);
#pragma unroll
                for (int i = 0; i < 20; i++) {
                    int f = i * 8 + q;
                    float4 v;
                    if (f < 128)      v = ldcg4(hp + f);
                    else if (f < 144) v = __ldg(xp + (f - 128));
                    else              v = ldcg4(pp + (f - 144));
                    dst[f] = v;
                }
            }
            __syncthreads();

            const int k = kb * 8 + warp;  // 0..511, uniform per warp
            const float4* wr = (const float4*)(g_wpack + (0 * Hz + k) * 640);
            const float4* wz = (const float4*)(g_wpack + (1 * Hz + k) * 640);
            const float4* wn = (const float4*)(g_wpack + (2 * Hz + k) * 640);
            const float4* hv = (const float4*)(sh + lane * PITCH);

            float ar  = g_bsum[k];
            float az  = g_bsum[Hz + k];
            float ahn = g_bhn[k];
            float ain = g_bin[k];

#pragma unroll 4
            for (int jj = 0; jj < 128; jj++) {   // h part (j < 512): n accum goes to gh_n
                float4 h4 = hv[jj];
                float4 w0 = __ldg(wr + jj);
                float4 w1 = __ldg(wz + jj);
                float4 w2 = __ldg(wn + jj);
                fma4(ar, h4, w0);
                fma4(az, h4, w1);
                fma4(ahn, h4, w2);
            }
#pragma unroll 4
            for (int jj = 128; jj < 160; jj++) { // x|pred part: n accum goes to gi_n
                float4 h4 = hv[jj];
                float4 w0 = __ldg(wr + jj);
                float4 w1 = __ldg(wz + jj);
                float4 w2 = __ldg(wn + jj);
                fma4(ar, h4, w0);
                fma4(az, h4, w1);
                fma4(ain, h4, w2);
            }

            float r    = sigmoidf_(ar);
            float z    = sigmoidf_(az);
            float n    = tanhf(ain + r * ahn);
            float hold = sh[lane * PITCH + k];  // h_{t-1}[b][k] (zeros at t=0)
            float hnew = (1.0f - z) * n + z * hold;
            g_outs[(size_t)t * Bz * Hz + (b0 + lane) * Hz + k] = hnew;
        }
        gsync(target);

        // ============================ Stage 2: a = relu(...) ===========================
        {
            const float* src = g_outs + (size_t)t * Bz * Hz;
            const int row = tid >> 3, q = tid & 7;
            const float4* hp = (const float4*)(src + (b0 + row) * Hz);
            float4* dst = (float4*)(sh + row * PITCH);
#pragma unroll
            for (int i = 0; i < 16; i++) dst[i * 8 + q] = ldcg4(hp + i * 8 + q);
            __syncthreads();

            const int k = kb * 8 + warp;
            const float4* w  = (const float4*)(cb_w1 + (size_t)k * Hz);
            const float4* hv = (const float4*)(sh + lane * PITCH);
            float acc = cb_b1[k];
#pragma unroll 4
            for (int jj = 0; jj < 128; jj++) {
                float4 h4 = hv[jj];
                float4 w4 = __ldg(w + jj);
                fma4(acc, h4, w4);
            }
            acc = fmaxf(acc, 0.0f);
            g_a[(b0 + lane) * Hz + k] = acc;
        }
        gsync(target);

        // ============================= Stage 3: pred ===================================
        if (bid < 16) {
            const int kb3 = bid >> 1;
            const int b03 = (bid & 1) * 32;
            const int row = tid >> 3, q = tid & 7;
            const float4* ap = (const float4*)(g_a + (b03 + row) * Hz);
            float4* dst = (float4*)(sh + row * PITCH);
#pragma unroll
            for (int i = 0; i < 16; i++) dst[i * 8 + q] = ldcg4(ap + i * 8 + q);
            __syncthreads();

            const int d = kb3 * 8 + warp;  // 0..63
            const float4* w  = (const float4*)(cb_w2 + (size_t)d * Hz);
            const float4* av = (const float4*)(sh + lane * PITCH);
            float acc = cb_b2[d];
#pragma unroll 4
            for (int jj = 0; jj < 128; jj++) {
                float4 a4 = av[jj];
                float4 w4 = __ldg(w + jj);
                fma4(acc, a4, w4);
            }
            out_cb[(size_t)(b03 + lane) * Sz * Dz + (size_t)t * Dz + d] = acc;
        }
        gsync(target);
    }

    // hidden output = h_{S-1}
    for (int idx = bid * NTHR + tid; idx < Bz * Hz; idx += NBLK * NTHR)
        out_hid[idx] = __ldcg(g_outs + (size_t)(Sz - 1) * Bz * Hz + idx);
}

// =====================================================================================
// Epilogue 1: ca1 = relu(outs @ fc_w^T + fc_b)   [65536 x 512], K=512
// Tiled fp32 GEMM: 64x64 block tile, 4x4 per thread, transposed smem tiles.
// outs rows are r = t*64 + b (layout [S,B,H]); output is [B,S,H].
// =====================================================================================
__global__ void __launch_bounds__(256) post1_kernel(
    const float* __restrict__ fc_w, const float* __restrict__ fc_b,
    float* __restrict__ out_ca1)
{
    __shared__ float As[16][64];
    __shared__ float Ws[16][64];
    const int r0 = blockIdx.y * 64;
    const int c0 = blockIdx.x * 64;
    const int tid = threadIdx.x;
    const int tx = tid & 15, ty = tid >> 4;

    float acc[4][4];
#pragma unroll
    for (int i = 0; i < 4; i++)
#pragma unroll
        for (int j = 0; j < 4; j++) acc[i][j] = 0.0f;

    const int li = tid >> 2;          // 0..63 row within tile
    const int lk = (tid & 3) * 4;     // 0,4,8,12 k-offset

    for (int k0 = 0; k0 < Hz; k0 += 16) {
        float4 av = *(const float4*)(g_outs + (size_t)(r0 + li) * Hz + k0 + lk);
        float4 wv = *(const float4*)(fc_w   + (size_t)(c0 + li) * Hz + k0 + lk);
        As[lk + 0][li] = av.x; As[lk + 1][li] = av.y; As[lk + 2][li] = av.z; As[lk + 3][li] = av.w;
        Ws[lk + 0][li] = wv.x; Ws[lk + 1][li] = wv.y; Ws[lk + 2][li] = wv.z; Ws[lk + 3][li] = wv.w;
        __syncthreads();
#pragma unroll
        for (int kk = 0; kk < 16; kk++) {
            float4 a4 = *(const float4*)(&As[kk][ty * 4]);
            float4 w4 = *(const float4*)(&Ws[kk][tx * 4]);
            acc[0][0] = fmaf(a4.x, w4.x, acc[0][0]); acc[0][1] = fmaf(a4.x, w4.y, acc[0][1]);
            acc[0][2] = fmaf(a4.x, w4.z, acc[0][2]); acc[0][3] = fmaf(a4.x, w4.w, acc[0][3]);
            acc[1][0] = fmaf(a4.y, w4.x, acc[1][0]); acc[1][1] = fmaf(a4.y, w4.y, acc[1][1]);
            acc[1][2] = fmaf(a4.y, w4.z, acc[1][2]); acc[1][3] = fmaf(a4.y, w4.w, acc[1][3]);
            acc[2][0] = fmaf(a4.z, w4.x, acc[2][0]); acc[2][1] = fmaf(a4.z, w4.y, acc[2][1]);
            acc[2][2] = fmaf(a4.z, w4.z, acc[2][2]); acc[2][3] = fmaf(a4.z, w4.w, acc[2][3]);
            acc[3][0] = fmaf(a4.w, w4.x, acc[3][0]); acc[3][1] = fmaf(a4.w, w4.y, acc[3][1]);
            acc[3][2] = fmaf(a4.w, w4.z, acc[3][2]); acc[3][3] = fmaf(a4.w, w4.w, acc[3][3]);
        }
        __syncthreads();
    }

    float4 bias = *(const float4*)(fc_b + c0 + tx * 4);
#pragma unroll
    for (int rr = 0; rr < 4; rr++) {
        int r = r0 + ty * 4 + rr;
        int b = r & 63;       // r = t*64 + b
        int t = r >> 6;
        float4 o;
        o.x = fmaxf(acc[rr][0] + bias.x, 0.0f);
        o.y = fmaxf(acc[rr][1] + bias.y, 0.0f);
        o.z = fmaxf(acc[rr][2] + bias.z, 0.0f);
        o.w = fmaxf(acc[rr][3] + bias.w, 0.0f);
        *(float4*)(out_ca1 + ((size_t)b * Sz + t) * Hz + c0 + tx * 4) = o;
    }
}

// =====================================================================================
// Epilogue 2: q = ca1 @ out_w^T + out_b   [65536 x 16], K=512
// out_w staged in smem; ca1 row broadcast across the 16 lanes sharing it.
// =====================================================================================
__global__ void __launch_bounds__(256) post2_kernel(
    const float* __restrict__ out_w, const float* __restrict__ out_b,
    const float* __restrict__ ca1, float* __restrict__ out_q)
{
    __shared__ float ws[Az * 516];
    const int tid = threadIdx.x;
    for (int f = tid; f < Az * 128; f += 256) {
        int a = f >> 7, jj = f & 127;
        float4 v = *(const float4*)(out_w + (size_t)a * Hz + jj * 4);
        *(float4*)(ws + a * 516 + jj * 4) = v;
    }
    __syncthreads();

    const int rl = tid >> 4, a = tid & 15;
    const int r = blockIdx.x * 16 + rl;   // row over [B,S] b-major, matches ca1/q layout
    const float4* cp = (const float4*)(ca1 + (size_t)r * Hz);
    const float4* wp = (const float4*)(ws + a * 516);
    float acc = out_b[a];
#pragma unroll 4
    for (int jj = 0; jj < 128; jj++) {
        float4 c4 = __ldg(cp + jj);
        float4 w4 = wp[jj];
        fma4(acc, c4, w4);
    }
    out_q[(size_t)r * Az + a] = acc;
}

// =====================================================================================
extern "C" void kernel_launch(void* const* d_in, const int* in_sizes, int n_in,
                              void* d_out, int out_size) {
    (void)in_sizes; (void)n_in; (void)out_size;
    const float* x     = (const float*)d_in[0];
    const float* W_ih  = (const float*)d_in[1];
    const float* W_hh  = (const float*)d_in[2];
    const float* b_ih  = (const float*)d_in[3];
    const float* b_hh  = (const float*)d_in[4];
    const float* fc_w  = (const float*)d_in[5];
    const float* fc_b  = (const float*)d_in[6];
    const float* out_w = (const float*)d_in[7];
    const float* out_b = (const float*)d_in[8];
    const float* cb_w1 = (const float*)d_in[9];
    const float* cb_b1 = (const float*)d_in[10];
    const float* cb_w2 = (const float*)d_in[11];
    const float* cb_b2 = (const float*)d_in[12];
    float* out = (float*)d_out;

    cudaFuncSetAttribute(recur_kernel, cudaFuncAttributeMaxDynamicSharedMemorySize, SMEM_BYTES);

    reset_kernel<<<1, 32>>>();
    recur_kernel<<<NBLK, NTHR, SMEM_BYTES>>>(x, W_ih, W_hh, b_ih, b_hh,
                                             cb_w1, cb_b1, cb_w2, cb_b2,
                                             out + CBOFF, out + HIDOFF);
    post1_kernel<<<dim3(8, 1024), 256>>>(fc_w, fc_b, out + CA1OFF);
    post2_kernel<<<4096, 256>>>(out_w, out_b, out + CA1OFF, out + QOFF);
}

// round 9
// speedup vs baseline: 1.0259x; 1.0259x over previous
#include <cuda_runtime.h>
#include <math.h>

// Problem dims
#define Bz 64
#define Sz 1024
#define Dz 64
#define Hz 512
#define Az 16

// Persistent kernel config
#define NBLK 128
#define NTHR 256
#define PITCH 644                            // smem row pitch in floats (%32==4 -> conflict-free LDS.128)
#define SMEM_FLOATS (32 * PITCH + 256)       // 32 activation rows + a_s[8][32]
#define SMEM_BYTES (SMEM_FLOATS * 4)         // 83456 B

// d_out layout: q [B,S,A] | cb_preds [B,S,D] | hidden [B,H] | ca1_out [B,S,H]
#define QOFF   0
#define CBOFF  (Bz * Sz * Az)
#define HIDOFF (CBOFF + Bz * Sz * Dz)
#define CA1OFF (HIDOFF + Bz * Hz)

// ---------------- device scratch (static __device__ only; no allocs) ----------------
__device__ float g_outs[Sz * Bz * Hz];   // h_t for all t, layout [t][b][j]
__device__ float g_wpack[3 * Hz * 640];  // packed gate weights [gate][k][j]; j: 0..511=h, 512..575=x, 576..639=pred
__device__ float g_bsum[2 * Hz];         // b_ih+b_hh for r,z gates
__device__ float g_bin[Hz];              // b_ih for n gate
__device__ float g_bhn[Hz];              // b_hh for n gate
__device__ float g_pred[2][Bz * Dz];     // parity-double-buffered pred accumulators [b][d]
__device__ unsigned long long g_barh[64];  // per-half barrier counters at [0] and [32]
__device__ unsigned long long g_bar_init;  // one-shot full-grid barrier

__global__ void reset_kernel() {
    int idx = blockIdx.x * blockDim.x + threadIdx.x;
    if (idx < 2 * Bz * Dz) ((float*)g_pred)[idx] = 0.0f;
    if (idx < 64) g_barh[idx] = 0ULL;
    if (idx == 64) g_bar_init = 0ULL;
}

__device__ __forceinline__ float4 ldcg4(const float4* p) { return __ldcg(p); }

// Per-half grid barrier (64 CTAs per half, all co-resident). No nanosleep.
__device__ __forceinline__ void gsync_half(int half, unsigned long long& target) {
    __syncthreads();
    if (threadIdx.x == 0) {
        __threadfence();
        target += 64ULL;
        atomicAdd(&g_barh[half * 32], 1ULL);
        while (*(volatile unsigned long long*)&g_barh[half * 32] < target) { }
        __threadfence();
    }
    __syncthreads();
}

// dot-product accumulate: acc += dot(va, vb)
__device__ __forceinline__ void fma4(float& acc, const float4 va, const float4 vb) {
    acc = fmaf(va.x, vb.x, acc);
    acc = fmaf(va.y, vb.y, acc);
    acc = fmaf(va.z, vb.z, acc);
    acc = fmaf(va.w, vb.w, acc);
}

__device__ __forceinline__ float sigmoidf_(float v) { return 1.0f / (1.0f + expf(-v)); }

// =====================================================================================
// Persistent recurrent kernel. 2 barriers per step, per batch-half.
// Stage1: h_new[32,512] per half from smem-resident [h | x_t | pred_{t-1}] (K=640)
// Stage2: a = relu(h_new @ cb_w1^T + cb_b1) (CTA-local in smem) + fused pred partial
//         reduction: RED atomics into g_pred[t&1][b][d].
// =====================================================================================
__global__ void __launch_bounds__(NTHR, 1) recur_kernel(
    const float* __restrict__ x,      // [B,S,D]
    const float* __restrict__ W_ih,   // [3H, 2D]
    const float* __restrict__ W_hh,   // [3H, H]
    const float* __restrict__ b_ih,   // [3H]
    const float* __restrict__ b_hh,   // [3H]
    const float* __restrict__ cb_w1,  // [H,H]
    const float* __restrict__ cb_b1,  // [H]
    const float* __restrict__ cb_w2,  // [D,H]
    const float* __restrict__ cb_b2,  // [D]
    float* __restrict__ out_cb,       // d_out + CBOFF  [B,S,D]
    float* __restrict__ out_hid)      // d_out + HIDOFF [B,H]
{
    extern __shared__ float sh[];  // 32 rows x PITCH floats, then a_s[8][32]
    float* a_s = sh + 32 * PITCH;
    const int tid  = threadIdx.x;
    const int bid  = blockIdx.x;
    const int lane = tid & 31;
    const int warp = tid >> 5;
    unsigned long long target = 0ULL;

    // ---------------- pack gate weights + biases ----------------
    for (int idx = bid * NTHR + tid; idx < 3 * Hz * 640; idx += NBLK * NTHR) {
        int j = idx % 640;
        int k = (idx / 640) % Hz;
        int g = idx / (640 * Hz);
        float v;
        if (j < 512) v = W_hh[(g * Hz + k) * Hz + j];
        else         v = W_ih[(g * Hz + k) * (2 * Dz) + (j - 512)];
        g_wpack[idx] = v;
    }
    for (int k = bid * NTHR + tid; k < Hz; k += NBLK * NTHR) {
        g_bsum[k]      = b_ih[k] + b_hh[k];
        g_bsum[Hz + k] = b_ih[Hz + k] + b_hh[Hz + k];
        g_bin[k]       = b_ih[2 * Hz + k];
        g_bhn[k]       = b_hh[2 * Hz + k];
    }
    // one-shot full-grid barrier (wpack is written grid-stride by everyone)
    __syncthreads();
    if (tid == 0) {
        __threadfence();
        atomicAdd(&g_bar_init, 1ULL);
        while (*(volatile unsigned long long*)&g_bar_init < (unsigned long long)NBLK) { }
        __threadfence();
    }
    __syncthreads();

    const int half = bid & 1;
    const int b0   = half * 32;      // batch half base
    const int kb   = bid >> 1;       // k-chunk (8 wide) index, 0..63
    const int k    = kb * 8 + warp;  // this warp's output unit, uniform per warp
    const int row  = tid >> 3;       // 0..31 staging row (= batch within half)
    const int q    = tid & 7;        // staging sub-slot
    const int bg   = b0 + row;

    // zero the h region of smem (h_{-1} = 0); rows [0..128) float4
    {
        float4 z4 = make_float4(0.f, 0.f, 0.f, 0.f);
        float4* dst = (float4*)(sh + row * PITCH);
#pragma unroll
        for (int i = 0; i < 16; i++) dst[i * 8 + q] = z4;
    }

    const float4* wr = (const float4*)(g_wpack + (0 * Hz + k) * 640);
    const float4* wz = (const float4*)(g_wpack + (1 * Hz + k) * 640);
    const float4* wn = (const float4*)(g_wpack + (2 * Hz + k) * 640);
    const float4* w1 = (const float4*)(cb_w1 + (size_t)k * Hz);
    const float bs_r = g_bsum[k];
    const float bs_z = g_bsum[Hz + k];
    const float bi_n = g_bin[k];
    const float bh_n = g_bhn[k];
    const float b1k  = cb_b1[k];

    for (int t = 0; t < Sz; t++) {
        const int pw = t & 1;          // accumulate parity this step
        const int pr = (t + 1) & 1;    // read parity (accumulated at t-1)

        // =========================== Stage 1 ===========================
        {
            // stage x_t into slots [128..144) and pred_{t-1} (+bias) into [144..160)
            float4* dst = (float4*)(sh + row * PITCH);
            const float4* xp = (const float4*)(x + ((size_t)bg * Sz + t) * Dz);
            dst[128 + q] = __ldg(xp + q);
            dst[136 + q] = __ldg(xp + 8 + q);
            if (t > 0) {
                const float4* pp = (const float4*)(g_pred[pr] + bg * Dz);
                float4 ba = __ldg((const float4*)(cb_b2 + 4 * q));
                float4 bb = __ldg((const float4*)(cb_b2 + 32 + 4 * q));
                float4 v0 = ldcg4(pp + q);
                float4 v1 = ldcg4(pp + 8 + q);
                v0.x += ba.x; v0.y += ba.y; v0.z += ba.z; v0.w += ba.w;
                v1.x += bb.x; v1.y += bb.y; v1.z += bb.z; v1.w += bb.w;
                dst[144 + q] = v0;
                dst[152 + q] = v1;
                if (kb == 0) {  // write pred_{t-1} output (includes bias)
                    float4* ob = (float4*)(out_cb + ((size_t)bg * Sz + (t - 1)) * Dz);
                    ob[q] = v0; ob[8 + q] = v1;
                }
            } else {
                float4 z4 = make_float4(0.f, 0.f, 0.f, 0.f);
                dst[144 + q] = z4;
                dst[152 + q] = z4;
            }
            __syncthreads();

            const float4* hv = (const float4*)(sh + lane * PITCH);
            float ar  = bs_r;
            float az  = bs_z;
            float ahn = bh_n;
            float ain = bi_n;

#pragma unroll 4
            for (int jj = 0; jj < 128; jj++) {   // h part: n goes to gh_n
                float4 h4 = hv[jj];
                float4 w0 = __ldg(wr + jj);
                float4 w1v = __ldg(wz + jj);
                float4 w2v = __ldg(wn + jj);
                fma4(ar, h4, w0);
                fma4(az, h4, w1v);
                fma4(ahn, h4, w2v);
            }
#pragma unroll 4
            for (int jj = 128; jj < 160; jj++) { // x|pred part: n goes to gi_n
                float4 h4 = hv[jj];
                float4 w0 = __ldg(wr + jj);
                float4 w1v = __ldg(wz + jj);
                float4 w2v = __ldg(wn + jj);
                fma4(ar, h4, w0);
                fma4(az, h4, w1v);
                fma4(ain, h4, w2v);
            }

            float r    = sigmoidf_(ar);
            float z    = sigmoidf_(az);
            float n    = tanhf(ain + r * ahn);
            float hold = sh[lane * PITCH + k];  // h_{t-1}[b0+lane][k]
            float hnew = (1.0f - z) * n + z * hold;
            g_outs[(size_t)t * Bz * Hz + (b0 + lane) * Hz + k] = hnew;
            if (t == Sz - 1) out_hid[(b0 + lane) * Hz + k] = hnew;
        }
        gsync_half(half, target);

        // =========================== Stage 2 (+fused pred) ===========================
        {
            // stage h_new (this also becomes stage1's h for t+1)
            const float* src = g_outs + (size_t)t * Bz * Hz;
            const float4* hp = (const float4*)(src + bg * Hz);
            float4* dst = (float4*)(sh + row * PITCH);
#pragma unroll
            for (int i = 0; i < 16; i++) dst[i * 8 + q] = ldcg4(hp + i * 8 + q);
            // reset the pred buffer that was read this step (ordered by mid barrier;
            // next accumulation into it is at t+1, ordered by end-of-step barrier)
            if (tid < 32) g_pred[pr][b0 * Dz + kb * 32 + tid] = 0.0f;
            __syncthreads();

            const float4* hv = (const float4*)(sh + lane * PITCH);
            float acc = b1k;
#pragma unroll 4
            for (int jj = 0; jj < 128; jj++) {
                float4 h4 = hv[jj];
                float4 w4 = __ldg(w1 + jj);
                fma4(acc, h4, w4);
            }
            acc = fmaxf(acc, 0.0f);
            a_s[warp * 32 + lane] = acc;  // a[k = kb*8+warp][b = lane]
            __syncthreads();

            // fused stage3: partial pred over this CTA's 8 k's, RED into g_pred[pw]
            float av0 = a_s[0 * 32 + lane], av1 = a_s[1 * 32 + lane];
            float av2 = a_s[2 * 32 + lane], av3 = a_s[3 * 32 + lane];
            float av4 = a_s[4 * 32 + lane], av5 = a_s[5 * 32 + lane];
            float av6 = a_s[6 * 32 + lane], av7 = a_s[7 * 32 + lane];
            const int k0 = kb * 8;
            float* predw = g_pred[pw] + (b0 + lane) * Dz;
#pragma unroll
            for (int d8 = 0; d8 < 8; d8++) {
                int d = warp * 8 + d8;
                float4 wa = __ldg((const float4*)(cb_w2 + (size_t)d * Hz + k0));
                float4 wb = __ldg((const float4*)(cb_w2 + (size_t)d * Hz + k0 + 4));
                float s = av0 * wa.x;
                s = fmaf(av1, wa.y, s);
                s = fmaf(av2, wa.z, s);
                s = fmaf(av3, wa.w, s);
                s = fmaf(av4, wb.x, s);
                s = fmaf(av5, wb.y, s);
                s = fmaf(av6, wb.z, s);
                s = fmaf(av7, wb.w, s);
                atomicAdd(predw + d, s);
            }
        }
        gsync_half(half, target);
    }

    // final pred output for t = Sz-1 (all contributions ordered by final barrier)
    if (kb == 0) {
        const int prf = (Sz - 1) & 1;
        const float4* pp = (const float4*)(g_pred[prf] + bg * Dz);
        float4 ba = __ldg((const float4*)(cb_b2 + 4 * q));
        float4 bb = __ldg((const float4*)(cb_b2 + 32 + 4 * q));
        float4 v0 = ldcg4(pp + q);
        float4 v1 = ldcg4(pp + 8 + q);
        v0.x += ba.x; v0.y += ba.y; v0.z += ba.z; v0.w += ba.w;
        v1.x += bb.x; v1.y += bb.y; v1.z += bb.z; v1.w += bb.w;
        float4* ob = (float4*)(out_cb + ((size_t)bg * Sz + (Sz - 1)) * Dz);
        ob[q] = v0; ob[8 + q] = v1;
    }
}

// =====================================================================================
// Epilogue 1: ca1 = relu(outs @ fc_w^T + fc_b)   [65536 x 512], K=512
// =====================================================================================
__global__ void __launch_bounds__(256) post1_kernel(
    const float* __restrict__ fc_w, const float* __restrict__ fc_b,
    float* __restrict__ out_ca1)
{
    __shared__ float As[16][64];
    __shared__ float Ws[16][64];
    const int r0 = blockIdx.y * 64;
    const int c0 = blockIdx.x * 64;
    const int tid = threadIdx.x;
    const int tx = tid & 15, ty = tid >> 4;

    float acc[4][4];
#pragma unroll
    for (int i = 0; i < 4; i++)
#pragma unroll
        for (int j = 0; j < 4; j++) acc[i][j] = 0.0f;

    const int li = tid >> 2;
    const int lk = (tid & 3) * 4;

    for (int k0 = 0; k0 < Hz; k0 += 16) {
        float4 av = *(const float4*)(g_outs + (size_t)(r0 + li) * Hz + k0 + lk);
        float4 wv = *(const float4*)(fc_w   + (size_t)(c0 + li) * Hz + k0 + lk);
        As[lk + 0][li] = av.x; As[lk + 1][li] = av.y; As[lk + 2][li] = av.z; As[lk + 3][li] = av.w;
        Ws[lk + 0][li] = wv.x; Ws[lk + 1][li] = wv.y; Ws[lk + 2][li] = wv.z; Ws[lk + 3][li] = wv.w;
        __syncthreads();
#pragma unroll
        for (int kk = 0; kk < 16; kk++) {
            float4 a4 = *(const float4*)(&As[kk][ty * 4]);
            float4 w4 = *(const float4*)(&Ws[kk][tx * 4]);
            acc[0][0] = fmaf(a4.x, w4.x, acc[0][0]); acc[0][1] = fmaf(a4.x, w4.y, acc[0][1]);
            acc[0][2] = fmaf(a4.x, w4.z, acc[0][2]); acc[0][3] = fmaf(a4.x, w4.w, acc[0][3]);
            acc[1][0] = fmaf(a4.y, w4.x, acc[1][0]); acc[1][1] = fmaf(a4.y, w4.y, acc[1][1]);
            acc[1][2] = fmaf(a4.y, w4.z, acc[1][2]); acc[1][3] = fmaf(a4.y, w4.w, acc[1][3]);
            acc[2][0] = fmaf(a4.z, w4.x, acc[2][0]); acc[2][1] = fmaf(a4.z, w4.y, acc[2][1]);
            acc[2][2] = fmaf(a4.z, w4.z, acc[2][2]); acc[2][3] = fmaf(a4.z, w4.w, acc[2][3]);
            acc[3][0] = fmaf(a4.w, w4.x, acc[3][0]); acc[3][1] = fmaf(a4.w, w4.y, acc[3][1]);
            acc[3][2] = fmaf(a4.w, w4.z, acc[3][2]); acc[3][3] = fmaf(a4.w, w4.w, acc[3][3]);
        }
        __syncthreads();
    }

    float4 bias = *(const float4*)(fc_b + c0 + tx * 4);
#pragma unroll
    for (int rr = 0; rr < 4; rr++) {
        int r = r0 + ty * 4 + rr;
        int b = r & 63;       // r = t*64 + b
        int t = r >> 6;
        float4 o;
        o.x = fmaxf(acc[rr][0] + bias.x, 0.0f);
        o.y = fmaxf(acc[rr][1] + bias.y, 0.0f);
        o.z = fmaxf(acc[rr][2] + bias.z, 0.0f);
        o.w = fmaxf(acc[rr][3] + bias.w, 0.0f);
        *(float4*)(out_ca1 + ((size_t)b * Sz + t) * Hz + c0 + tx * 4) = o;
    }
}

// =====================================================================================
// Epilogue 2: q = ca1 @ out_w^T + out_b   [65536 x 16], K=512
// =====================================================================================
__global__ void __launch_bounds__(256) post2_kernel(
    const float* __restrict__ out_w, const float* __restrict__ out_b,
    const float* __restrict__ ca1, float* __restrict__ out_q)
{
    __shared__ float ws[Az * 516];
    const int tid = threadIdx.x;
    for (int f = tid; f < Az * 128; f += 256) {
        int a = f >> 7, jj = f & 127;
        float4 v = *(const float4*)(out_w + (size_t)a * Hz + jj * 4);
        *(float4*)(ws + a * 516 + jj * 4) = v;
    }
    __syncthreads();

    const int rl = tid >> 4, a = tid & 15;
    const int r = blockIdx.x * 16 + rl;
    const float4* cp = (const float4*)(ca1 + (size_t)r * Hz);
    const float4* wp = (const float4*)(ws + a * 516);
    float acc = out_b[a];
#pragma unroll 4
    for (int jj = 0; jj < 128; jj++) {
        float4 c4 = __ldg(cp + jj);
        float4 w4 = wp[jj];
        fma4(acc, c4, w4);
    }
    out_q[(size_t)r * Az + a] = acc;
}

// =====================================================================================
extern "C" void kernel_launch(void* const* d_in, const int* in_sizes, int n_in,
                              void* d_out, int out_size) {
    (void)in_sizes; (void)n_in; (void)out_size;
    const float* x     = (const float*)d_in[0];
    const float* W_ih  = (const float*)d_in[1];
    const float* W_hh  = (const float*)d_in[2];
    const float* b_ih  = (const float*)d_in[3];
    const float* b_hh  = (const float*)d_in[4];
    const float* fc_w  = (const float*)d_in[5];
    const float* fc_b  = (const float*)d_in[6];
    const float* out_w = (const float*)d_in[7];
    const float* out_b = (const float*)d_in[8];
    const float* cb_w1 = (const float*)d_in[9];
    const float* cb_b1 = (const float*)d_in[10];
    const float* cb_w2 = (const float*)d_in[11];
    const float* cb_b2 = (const float*)d_in[12];
    float* out = (float*)d_out;

    cudaFuncSetAttribute(recur_kernel, cudaFuncAttributeMaxDynamicSharedMemorySize, SMEM_BYTES);

    reset_kernel<<<33, 256>>>();
    recur_kernel<<<NBLK, NTHR, SMEM_BYTES>>>(x, W_ih, W_hh, b_ih, b_hh,
                                             cb_w1, cb_b1, cb_w2, cb_b2,
                                             out + CBOFF, out + HIDOFF);
    post1_kernel<<<dim3(8, 1024), 256>>>(fc_w, fc_b, out + CA1OFF);
    post2_kernel<<<4096, 256>>>(out_w, out_b, out + CA1OFF, out + QOFF);
}

// round 10
// speedup vs baseline: 1.0879x; 1.0604x over previous
#include <cuda_runtime.h>
#include <math.h>

// Problem dims
#define Bz 64
#define Sz 1024
#define Dz 64
#define Hz 512
#define Az 16

// Persistent kernel config
#define NBLK 128
#define NTHR 256
#define PITCH 644                            // smem row pitch in floats (%32==4 -> conflict-free LDS.128)
#define SMEM_FLOATS (32 * PITCH + 256)       // 32 activation rows + a_s[8][32]
#define SMEM_BYTES (SMEM_FLOATS * 4)         // 83456 B

// d_out layout: q [B,S,A] | cb_preds [B,S,D] | hidden [B,H] | ca1_out [B,S,H]
#define QOFF   0
#define CBOFF  (Bz * Sz * Az)
#define HIDOFF (CBOFF + Bz * Sz * Dz)
#define CA1OFF (HIDOFF + Bz * Hz)

// ---------------- device scratch (static __device__ only; no allocs) ----------------
__device__ float g_outs[Sz * Bz * Hz];   // h_t for all t, layout [t][b][j]
__device__ float g_wpack[3 * Hz * 640];  // packed gate weights [gate][k][j]; j: 0..511=h, 512..575=x, 576..639=pred
__device__ float g_bsum[2 * Hz];         // b_ih+b_hh for r,z gates
__device__ float g_bin[Hz];              // b_ih for n gate
__device__ float g_bhn[Hz];              // b_hh for n gate
__device__ float g_pred[2][Bz * Dz];     // parity-double-buffered pred accumulators [b][d]
__device__ unsigned long long g_barh[64];  // per-half barrier counters at [0] and [32]
__device__ unsigned long long g_bar_init;  // one-shot full-grid barrier

__global__ void reset_kernel() {
    int idx = blockIdx.x * blockDim.x + threadIdx.x;
    if (idx < 2 * Bz * Dz) ((float*)g_pred)[idx] = 0.0f;
    if (idx < 64) g_barh[idx] = 0ULL;
    if (idx == 64) g_bar_init = 0ULL;
}

// No-op launch-slot shifters so ncu (-s 5 -c 1) lands on recur_kernel.
__global__ void noop_a_kernel() {}
__global__ void noop_b_kernel() {}

__device__ __forceinline__ float4 ldcg4(const float4* p) { return __ldcg(p); }

// ---------------- packed f32x2 helpers ----------------
typedef unsigned long long u64;

__device__ __forceinline__ u64 pk2(float lo, float hi) {
    u64 r;
    asm("mov.b64 %0, {%1, %2};" : "=l"(r) : "f"(lo), "f"(hi));
    return r;
}
__device__ __forceinline__ void upk2(u64 v, float& lo, float& hi) {
    asm("mov.b64 {%0, %1}, %2;" : "=f"(lo), "=f"(hi) : "l"(v));
}
// acc = a*b + acc on packed f32x2 (one FFMA2 instruction)
__device__ __forceinline__ void fma2(u64& acc, u64 a, u64 b) {
    asm("fma.rn.f32x2 %0, %1, %2, %3;" : "=l"(acc) : "l"(a), "l"(b), "l"(acc));
}
// 128-bit non-coherent global load as two u64
__device__ __forceinline__ ulonglong2 ldg2(const ulonglong2* p) {
    ulonglong2 r;
    asm("ld.global.nc.v2.u64 {%0, %1}, [%2];" : "=l"(r.x), "=l"(r.y) : "l"(p));
    return r;
}

// Per-half grid barrier (64 CTAs per half, all co-resident).
__device__ __forceinline__ void gsync_half(int half, unsigned long long& target) {
    __syncthreads();
    if (threadIdx.x == 0) {
        __threadfence();
        target += 64ULL;
        atomicAdd(&g_barh[half * 32], 1ULL);
        while (*(volatile unsigned long long*)&g_barh[half * 32] < target) { }
        __threadfence();
    }
    __syncthreads();
}

// dot-product accumulate: acc += dot(va, vb)
__device__ __forceinline__ void fma4(float& acc, const float4 va, const float4 vb) {
    acc = fmaf(va.x, vb.x, acc);
    acc = fmaf(va.y, vb.y, acc);
    acc = fmaf(va.z, vb.z, acc);
    acc = fmaf(va.w, vb.w, acc);
}

__device__ __forceinline__ float sigmoidf_(float v) { return 1.0f / (1.0f + expf(-v)); }

// =====================================================================================
// Persistent recurrent kernel. 2 barriers per step, per batch-half.
// Stage1: h_new[32,512] per half from smem-resident [h | x_t | pred_{t-1}] (K=640)
// Stage2: a = relu(h_new @ cb_w1^T + cb_b1) + fused pred partial reduction (REDG).
// Inner products use packed fma.rn.f32x2 (FFMA2) with u64-pair loads.
// =====================================================================================
__global__ void __launch_bounds__(NTHR, 1) recur_kernel(
    const float* __restrict__ x,      // [B,S,D]
    const float* __restrict__ W_ih,   // [3H, 2D]
    const float* __restrict__ W_hh,   // [3H, H]
    const float* __restrict__ b_ih,   // [3H]
    const float* __restrict__ b_hh,   // [3H]
    const float* __restrict__ cb_w1,  // [H,H]
    const float* __restrict__ cb_b1,  // [H]
    const float* __restrict__ cb_w2,  // [D,H]
    const float* __restrict__ cb_b2,  // [D]
    float* __restrict__ out_cb,       // d_out + CBOFF  [B,S,D]
    float* __restrict__ out_hid)      // d_out + HIDOFF [B,H]
{
    extern __shared__ float sh[];  // 32 rows x PITCH floats, then a_s[8][32]
    float* a_s = sh + 32 * PITCH;
    const int tid  = threadIdx.x;
    const int bid  = blockIdx.x;
    const int lane = tid & 31;
    const int warp = tid >> 5;
    unsigned long long target = 0ULL;

    // ---------------- pack gate weights + biases ----------------
    for (int idx = bid * NTHR + tid; idx < 3 * Hz * 640; idx += NBLK * NTHR) {
        int j = idx % 640;
        int k = (idx / 640) % Hz;
        int g = idx / (640 * Hz);
        float v;
        if (j < 512) v = W_hh[(g * Hz + k) * Hz + j];
        else         v = W_ih[(g * Hz + k) * (2 * Dz) + (j - 512)];
        g_wpack[idx] = v;
    }
    for (int k = bid * NTHR + tid; k < Hz; k += NBLK * NTHR) {
        g_bsum[k]      = b_ih[k] + b_hh[k];
        g_bsum[Hz + k] = b_ih[Hz + k] + b_hh[Hz + k];
        g_bin[k]       = b_ih[2 * Hz + k];
        g_bhn[k]       = b_hh[2 * Hz + k];
    }
    // one-shot full-grid barrier
    __syncthreads();
    if (tid == 0) {
        __threadfence();
        atomicAdd(&g_bar_init, 1ULL);
        while (*(volatile unsigned long long*)&g_bar_init < (unsigned long long)NBLK) { }
        __threadfence();
    }
    __syncthreads();

    const int half = bid & 1;
    const int b0   = half * 32;      // batch half base
    const int kb   = bid >> 1;       // k-chunk (8 wide) index, 0..63
    const int k    = kb * 8 + warp;  // this warp's output unit, uniform per warp
    const int row  = tid >> 3;       // 0..31 staging row (= batch within half)
    const int q    = tid & 7;        // staging sub-slot
    const int bg   = b0 + row;

    // zero the h region of smem (h_{-1} = 0); rows [0..128) float4
    {
        float4 z4 = make_float4(0.f, 0.f, 0.f, 0.f);
        float4* dst = (float4*)(sh + row * PITCH);
#pragma unroll
        for (int i = 0; i < 16; i++) dst[i * 8 + q] = z4;
    }

    const ulonglong2* wr2 = (const ulonglong2*)(g_wpack + (0 * Hz + k) * 640);
    const ulonglong2* wz2 = (const ulonglong2*)(g_wpack + (1 * Hz + k) * 640);
    const ulonglong2* wn2 = (const ulonglong2*)(g_wpack + (2 * Hz + k) * 640);
    const ulonglong2* w12 = (const ulonglong2*)(cb_w1 + (size_t)k * Hz);
    const float bs_r = g_bsum[k];
    const float bs_z = g_bsum[Hz + k];
    const float bi_n = g_bin[k];
    const float bh_n = g_bhn[k];
    const float b1k  = cb_b1[k];

    for (int t = 0; t < Sz; t++) {
        const int pw = t & 1;          // accumulate parity this step
        const int pr = (t + 1) & 1;    // read parity (accumulated at t-1)

        // =========================== Stage 1 ===========================
        {
            // stage x_t into slots [128..144) and pred_{t-1} (+bias) into [144..160)
            float4* dst = (float4*)(sh + row * PITCH);
            const float4* xp = (const float4*)(x + ((size_t)bg * Sz + t) * Dz);
            dst[128 + q] = __ldg(xp + q);
            dst[136 + q] = __ldg(xp + 8 + q);
            if (t > 0) {
                const float4* pp = (const float4*)(g_pred[pr] + bg * Dz);
                float4 ba = __ldg((const float4*)(cb_b2 + 4 * q));
                float4 bb = __ldg((const float4*)(cb_b2 + 32 + 4 * q));
                float4 v0 = ldcg4(pp + q);
                float4 v1 = ldcg4(pp + 8 + q);
                v0.x += ba.x; v0.y += ba.y; v0.z += ba.z; v0.w += ba.w;
                v1.x += bb.x; v1.y += bb.y; v1.z += bb.z; v1.w += bb.w;
                dst[144 + q] = v0;
                dst[152 + q] = v1;
                if (kb == 0) {  // write pred_{t-1} output (includes bias)
                    float4* ob = (float4*)(out_cb + ((size_t)bg * Sz + (t - 1)) * Dz);
                    ob[q] = v0; ob[8 + q] = v1;
                }
            } else {
                float4 z4 = make_float4(0.f, 0.f, 0.f, 0.f);
                dst[144 + q] = z4;
                dst[152 + q] = z4;
            }
            __syncthreads();

            const ulonglong2* hv2 = (const ulonglong2*)(sh + lane * PITCH);
            // 8 packed accumulators (a/b halves of each gate) -> shallow chains
            u64 ar_a = pk2(bs_r, 0.f), ar_b = pk2(0.f, 0.f);
            u64 az_a = pk2(bs_z, 0.f), az_b = pk2(0.f, 0.f);
            u64 an_a = pk2(bh_n, 0.f), an_b = pk2(0.f, 0.f);  // h-part of n
            u64 ai_a = pk2(bi_n, 0.f), ai_b = pk2(0.f, 0.f);  // x|pred-part of n

#pragma unroll 4
            for (int jj = 0; jj < 128; jj++) {   // h part: n goes to gh_n
                ulonglong2 h2 = hv2[jj];
                ulonglong2 w0 = ldg2(wr2 + jj);
                ulonglong2 w1v = ldg2(wz2 + jj);
                ulonglong2 w2v = ldg2(wn2 + jj);
                fma2(ar_a, h2.x, w0.x);  fma2(ar_b, h2.y, w0.y);
                fma2(az_a, h2.x, w1v.x); fma2(az_b, h2.y, w1v.y);
                fma2(an_a, h2.x, w2v.x); fma2(an_b, h2.y, w2v.y);
            }
#pragma unroll 4
            for (int jj = 128; jj < 160; jj++) { // x|pred part: n goes to gi_n
                ulonglong2 h2 = hv2[jj];
                ulonglong2 w0 = ldg2(wr2 + jj);
                ulonglong2 w1v = ldg2(wz2 + jj);
                ulonglong2 w2v = ldg2(wn2 + jj);
                fma2(ar_a, h2.x, w0.x);  fma2(ar_b, h2.y, w0.y);
                fma2(az_a, h2.x, w1v.x); fma2(az_b, h2.y, w1v.y);
                fma2(ai_a, h2.x, w2v.x); fma2(ai_b, h2.y, w2v.y);
            }

            float l0, h0, l1, h1;
            upk2(ar_a, l0, h0); upk2(ar_b, l1, h1);
            float ar = (l0 + h0) + (l1 + h1);
            upk2(az_a, l0, h0); upk2(az_b, l1, h1);
            float az = (l0 + h0) + (l1 + h1);
            upk2(an_a, l0, h0); upk2(an_b, l1, h1);
            float ahn = (l0 + h0) + (l1 + h1);
            upk2(ai_a, l0, h0); upk2(ai_b, l1, h1);
            float ain = (l0 + h0) + (l1 + h1);

            float r    = sigmoidf_(ar);
            float z    = sigmoidf_(az);
            float n    = tanhf(ain + r * ahn);
            float hold = sh[lane * PITCH + k];  // h_{t-1}[b0+lane][k]
            float hnew = (1.0f - z) * n + z * hold;
            g_outs[(size_t)t * Bz * Hz + (b0 + lane) * Hz + k] = hnew;
            if (t == Sz - 1) out_hid[(b0 + lane) * Hz + k] = hnew;
        }
        gsync_half(half, target);

        // =========================== Stage 2 (+fused pred) ===========================
        {
            // stage h_new (this also becomes stage1's h for t+1)
            const float* src = g_outs + (size_t)t * Bz * Hz;
            const float4* hp = (const float4*)(src + bg * Hz);
            float4* dst = (float4*)(sh + row * PITCH);
#pragma unroll
            for (int i = 0; i < 16; i++) dst[i * 8 + q] = ldcg4(hp + i * 8 + q);
            // reset the pred buffer that was read this step
            if (tid < 32) g_pred[pr][b0 * Dz + kb * 32 + tid] = 0.0f;
            __syncthreads();

            const ulonglong2* hv2 = (const ulonglong2*)(sh + lane * PITCH);
            u64 ac_a = pk2(b1k, 0.f), ac_b = pk2(0.f, 0.f);
#pragma unroll 4
            for (int jj = 0; jj < 128; jj++) {
                ulonglong2 h2 = hv2[jj];
                ulonglong2 w4 = ldg2(w12 + jj);
                fma2(ac_a, h2.x, w4.x);
                fma2(ac_b, h2.y, w4.y);
            }
            float l0, h0, l1, h1;
            upk2(ac_a, l0, h0); upk2(ac_b, l1, h1);
            float acc = (l0 + h0) + (l1 + h1);
            acc = fmaxf(acc, 0.0f);
            a_s[warp * 32 + lane] = acc;  // a[k = kb*8+warp][b = lane]
            __syncthreads();

            // fused stage3: partial pred over this CTA's 8 k's, RED into g_pred[pw]
            float av0 = a_s[0 * 32 + lane], av1 = a_s[1 * 32 + lane];
            float av2 = a_s[2 * 32 + lane], av3 = a_s[3 * 32 + lane];
            float av4 = a_s[4 * 32 + lane], av5 = a_s[5 * 32 + lane];
            float av6 = a_s[6 * 32 + lane], av7 = a_s[7 * 32 + lane];
            const int k0 = kb * 8;
            float* predw = g_pred[pw] + (b0 + lane) * Dz;
#pragma unroll
            for (int d8 = 0; d8 < 8; d8++) {
                int d = warp * 8 + d8;
                float4 wa = __ldg((const float4*)(cb_w2 + (size_t)d * Hz + k0));
                float4 wb = __ldg((const float4*)(cb_w2 + (size_t)d * Hz + k0 + 4));
                float s = av0 * wa.x;
                s = fmaf(av1, wa.y, s);
                s = fmaf(av2, wa.z, s);
                s = fmaf(av3, wa.w, s);
                s = fmaf(av4, wb.x, s);
                s = fmaf(av5, wb.y, s);
                s = fmaf(av6, wb.z, s);
                s = fmaf(av7, wb.w, s);
                atomicAdd(predw + d, s);
            }
        }
        gsync_half(half, target);
    }

    // final pred output for t = Sz-1
    if (kb == 0) {
        const int prf = (Sz - 1) & 1;
        const float4* pp = (const float4*)(g_pred[prf] + bg * Dz);
        float4 ba = __ldg((const float4*)(cb_b2 + 4 * q));
        float4 bb = __ldg((const float4*)(cb_b2 + 32 + 4 * q));
        float4 v0 = ldcg4(pp + q);
        float4 v1 = ldcg4(pp + 8 + q);
        v0.x += ba.x; v0.y += ba.y; v0.z += ba.z; v0.w += ba.w;
        v1.x += bb.x; v1.y += bb.y; v1.z += bb.z; v1.w += bb.w;
        float4* ob = (float4*)(out_cb + ((size_t)bg * Sz + (Sz - 1)) * Dz);
        ob[q] = v0; ob[8 + q] = v1;
    }
}

// =====================================================================================
// Epilogue 1: ca1 = relu(outs @ fc_w^T + fc_b)   [65536 x 512], K=512
// =====================================================================================
__global__ void __launch_bounds__(256) post1_kernel(
    const float* __restrict__ fc_w, const float* __restrict__ fc_b,
    float* __restrict__ out_ca1)
{
    __shared__ float As[16][64];
    __shared__ float Ws[16][64];
    const int r0 = blockIdx.y * 64;
    const int c0 = blockIdx.x * 64;
    const int tid = threadIdx.x;
    const int tx = tid & 15, ty = tid >> 4;

    float acc[4][4];
#pragma unroll
    for (int i = 0; i < 4; i++)
#pragma unroll
        for (int j = 0; j < 4; j++) acc[i][j] = 0.0f;

    const int li = tid >> 2;
    const int lk = (tid & 3) * 4;

    for (int k0 = 0; k0 < Hz; k0 += 16) {
        float4 av = *(const float4*)(g_outs + (size_t)(r0 + li) * Hz + k0 + lk);
        float4 wv = *(const float4*)(fc_w   + (size_t)(c0 + li) * Hz + k0 + lk);
        As[lk + 0][li] = av.x; As[lk + 1][li] = av.y; As[lk + 2][li] = av.z; As[lk + 3][li] = av.w;
        Ws[lk + 0][li] = wv.x; Ws[lk + 1][li] = wv.y; Ws[lk + 2][li] = wv.z; Ws[lk + 3][li] = wv.w;
        __syncthreads();
#pragma unroll
        for (int kk = 0; kk < 16; kk++) {
            float4 a4 = *(const float4*)(&As[kk][ty * 4]);
            float4 w4 = *(const float4*)(&Ws[kk][tx * 4]);
            acc[0][0] = fmaf(a4.x, w4.x, acc[0][0]); acc[0][1] = fmaf(a4.x, w4.y, acc[0][1]);
            acc[0][2] = fmaf(a4.x, w4.z, acc[0][2]); acc[0][3] = fmaf(a4.x, w4.w, acc[0][3]);
            acc[1][0] = fmaf(a4.y, w4.x, acc[1][0]); acc[1][1] = fmaf(a4.y, w4.y, acc[1][1]);
            acc[1][2] = fmaf(a4.y, w4.z, acc[1][2]); acc[1][3] = fmaf(a4.y, w4.w, acc[1][3]);
            acc[2][0] = fmaf(a4.z, w4.x, acc[2][0]); acc[2][1] = fmaf(a4.z, w4.y, acc[2][1]);
            acc[2][2] = fmaf(a4.z, w4.z, acc[2][2]); acc[2][3] = fmaf(a4.z, w4.w, acc[2][3]);
            acc[3][0] = fmaf(a4.w, w4.x, acc[3][0]); acc[3][1] = fmaf(a4.w, w4.y, acc[3][1]);
            acc[3][2] = fmaf(a4.w, w4.z, acc[3][2]); acc[3][3] = fmaf(a4.w, w4.w, acc[3][3]);
        }
        __syncthreads();
    }

    float4 bias = *(const float4*)(fc_b + c0 + tx * 4);
#pragma unroll
    for (int rr = 0; rr < 4; rr++) {
        int r = r0 + ty * 4 + rr;
        int b = r & 63;       // r = t*64 + b
        int t = r >> 6;
        float4 o;
        o.x = fmaxf(acc[rr][0] + bias.x, 0.0f);
        o.y = fmaxf(acc[rr][1] + bias.y, 0.0f);
        o.z = fmaxf(acc[rr][2] + bias.z, 0.0f);
        o.w = fmaxf(acc[rr][3] + bias.w, 0.0f);
        *(float4*)(out_ca1 + ((size_t)b * Sz + t) * Hz + c0 + tx * 4) = o;
    }
}

// =====================================================================================
// Epilogue 2: q = ca1 @ out_w^T + out_b   [65536 x 16], K=512
// =====================================================================================
__global__ void __launch_bounds__(256) post2_kernel(
    const float* __restrict__ out_w, const float* __restrict__ out_b,
    const float* __restrict__ ca1, float* __restrict__ out_q)
{
    __shared__ float ws[Az * 516];
    const int tid = threadIdx.x;
    for (int f = tid; f < Az * 128; f += 256) {
        int a = f >> 7, jj = f & 127;
        float4 v = *(const float4*)(out_w + (size_t)a * Hz + jj * 4);
        *(float4*)(ws + a * 516 + jj * 4) = v;
    }
    __syncthreads();

    const int rl = tid >> 4, a = tid & 15;
    const int r = blockIdx.x * 16 + rl;
    const float4* cp = (const float4*)(ca1 + (size_t)r * Hz);
    const float4* wp = (const float4*)(ws + a * 516);
    float acc = out_b[a];
#pragma unroll 4
    for (int jj = 0; jj < 128; jj++) {
        float4 c4 = __ldg(cp + jj);
        float4 w4 = wp[jj];
        fma4(acc, c4, w4);
    }
    out_q[(size_t)r * Az + a] = acc;
}

// =====================================================================================
extern "C" void kernel_launch(void* const* d_in, const int* in_sizes, int n_in,
                              void* d_out, int out_size) {
    (void)in_sizes; (void)n_in; (void)out_size;
    const float* x     = (const float*)d_in[0];
    const float* W_ih  = (const float*)d_in[1];
    const float* W_hh  = (const float*)d_in[2];
    const float* b_ih  = (const float*)d_in[3];
    const float* b_hh  = (const float*)d_in[4];
    const float* fc_w  = (const float*)d_in[5];
    const float* fc_b  = (const float*)d_in[6];
    const float* out_w = (const float*)d_in[7];
    const float* out_b = (const float*)d_in[8];
    const float* cb_w1 = (const float*)d_in[9];
    const float* cb_b1 = (const float*)d_in[10];
    const float* cb_w2 = (const float*)d_in[11];
    const float* cb_b2 = (const float*)d_in[12];
    float* out = (float*)d_out;

    cudaFuncSetAttribute(recur_kernel, cudaFuncAttributeMaxDynamicSharedMemorySize, SMEM_BYTES);

    reset_kernel<<<33, 256>>>();
    noop_a_kernel<<<1, 1>>>();   // launch-slot shifters: put recur at ncu's -s 5 slot
    noop_b_kernel<<<1, 1>>>();
    recur_kernel<<<NBLK, NTHR, SMEM_BYTES>>>(x, W_ih, W_hh, b_ih, b_hh,
                                             cb_w1, cb_b1, cb_w2, cb_b2,
                                             out + CBOFF, out + HIDOFF);
    post1_kernel<<<dim3(8, 1024), 256>>>(fc_w, fc_b, out + CA1OFF);
    post2_kernel<<<4096, 256>>>(out_w, out_b, out + CA1OFF, out + QOFF);
}